// round 15
// baseline (speedup 1.0000x reference)
#include <cuda_runtime.h>
#include <cuda_fp16.h>
#include <cstdint>
#include <cstddef>

// Problem constants
#define NB   4
#define TLEN 2048
#define DMODEL 1024
#define NH   16
#define DK   64
#define MROWS (NB * TLEN)        // 8192
#define QKVCOLS (3 * DMODEL)     // 3072

// Q pre-scale: 1/sqrt(64) * log2(e)  (softmax runs in exp2 domain)
#define QSCALE 0.1803368801111204f

// Scratch (device globals) — fp16 datapath
__device__ __half g_qkv[(size_t)MROWS * QKVCOLS];       // 50.3 MB (Q pre-scaled)
__device__ __half g_att[(size_t)MROWS * DMODEL];        // 16.8 MB
__device__ __half g_zr[(size_t)MROWS * DMODEL];         // 16.8 MB
__device__ __half g_wtqkv[(size_t)QKVCOLS * DMODEL];    // 6.3 MB
__device__ __half g_wtout[(size_t)DMODEL * DMODEL];     // 2.1 MB

__device__ __forceinline__ float ex2(float x) {
    float y;
    asm("ex2.approx.f32 %0, %1;" : "=f"(y) : "f"(x));
    return y;
}

__device__ __forceinline__ uint32_t smem_u32(const void* p) {
    uint32_t a;
    asm("{ .reg .u64 t; cvta.to.shared.u64 t, %1; cvt.u32.u64 %0, t; }"
        : "=r"(a) : "l"(p));
    return a;
}

__device__ __forceinline__ void cp16(uint32_t dst, const void* src) {
    asm volatile("cp.async.cg.shared.global [%0], [%1], 16;"
                 :: "r"(dst), "l"(src));
}
#define CP_COMMIT() asm volatile("cp.async.commit_group;" ::: "memory")
#define CP_WAIT0()  asm volatile("cp.async.wait_group 0;" ::: "memory")
#define CP_WAIT1()  asm volatile("cp.async.wait_group 1;" ::: "memory")

__device__ __forceinline__ void ldsm_x4(uint32_t* r, uint32_t addr) {
    asm volatile("ldmatrix.sync.aligned.m8n8.x4.shared.b16 {%0,%1,%2,%3}, [%4];"
                 : "=r"(r[0]), "=r"(r[1]), "=r"(r[2]), "=r"(r[3]) : "r"(addr));
}

__device__ __forceinline__ void ldsm_x4_trans(uint32_t* r, uint32_t addr) {
    asm volatile("ldmatrix.sync.aligned.m8n8.x4.trans.shared.b16 {%0,%1,%2,%3}, [%4];"
                 : "=r"(r[0]), "=r"(r[1]), "=r"(r[2]), "=r"(r[3]) : "r"(addr));
}

__device__ __forceinline__ uint32_t h2u(float a, float b) {
    __half2 h = __floats2half2_rn(a, b);
    return *reinterpret_cast<uint32_t*>(&h);
}

// f32-accum MMA (GEMMs)
#define MMA_F16(c, a, b)                                                      \
    asm volatile(                                                             \
        "mma.sync.aligned.m16n8k16.row.col.f32.f16.f16.f32 "                  \
        "{%0,%1,%2,%3}, {%4,%5,%6,%7}, {%8,%9}, {%0,%1,%2,%3};"               \
        : "+f"((c)[0]), "+f"((c)[1]), "+f"((c)[2]), "+f"((c)[3])              \
        : "r"((a)[0]), "r"((a)[1]), "r"((a)[2]), "r"((a)[3]),                 \
          "r"((b)[0]), "r"((b)[1]))

// f16-accum MMA (attention; potentially double-rate on legacy pipe)
#define MMA_F16A16(c, a, b)                                                   \
    asm volatile(                                                             \
        "mma.sync.aligned.m16n8k16.row.col.f16.f16.f16.f16 "                  \
        "{%0,%1}, {%2,%3,%4,%5}, {%6,%7}, {%0,%1};"                           \
        : "+r"((c)[0]), "+r"((c)[1])                                          \
        : "r"((a)[0]), "r"((a)[1]), "r"((a)[2]), "r"((a)[3]),                 \
          "r"((b)[0]), "r"((b)[1]))

__device__ __forceinline__ float2 u2f2(uint32_t u) {
    __half2 h = *reinterpret_cast<__half2*>(&u);
    return __half22float2(h);
}

// ===========================================================================
// z (fp32) -> fp16 copy
// ===========================================================================
__global__ __launch_bounds__(256)
void round_copy_kernel(const float4* __restrict__ in, __half2* __restrict__ out, int n4)
{
    int i = blockIdx.x * blockDim.x + threadIdx.x;
    if (i < n4) {
        float4 v = in[i];
        out[2 * i]     = __floats2half2_rn(v.x, v.y);
        out[2 * i + 1] = __floats2half2_rn(v.z, v.w);
    }
}

// ===========================================================================
// Weight transpose + fp16
// ===========================================================================
__global__ __launch_bounds__(256)
void transpose_round_kernel(const float* __restrict__ W, __half* __restrict__ WT,
                            int K, int N)
{
    __shared__ float tile[32][33];
    const int bx = blockIdx.x * 32;
    const int by = blockIdx.y * 32;
    const int tx = threadIdx.x;
    const int ty = threadIdx.y;
#pragma unroll
    for (int i = 0; i < 32; i += 8)
        tile[ty + i][tx] = W[(size_t)(by + ty + i) * N + bx + tx];
    __syncthreads();
#pragma unroll
    for (int i = 0; i < 32; i += 8)
        WT[(size_t)(bx + ty + i) * K + by + tx] = __float2half_rn(tile[tx][ty + i]);
}

// ===========================================================================
// 3-stage pipelined fp16 GEMM, CTA 128x128, BK=64 (round-14 verified best)
// ===========================================================================
#define ASTR 72
#define NSTAGE 3
#define OBUFH (128 * ASTR)
#define GEMM_SMEM (NSTAGE * 2 * OBUFH * 2)   // 110592 B

template <int OUT_HALF>
__global__ __launch_bounds__(256, 2)
void f16_gemm_kernel(const __half* __restrict__ A, const __half* __restrict__ BT,
                     void* __restrict__ Cout, int M, int N, int K,
                     int qlimit, float qscale)
{
    extern __shared__ __half hs[];
    __half* sA = hs;
    __half* sB = hs + NSTAGE * OBUFH;

    const int tid = threadIdx.x;
    const int wid = tid >> 5;
    const int lane = tid & 31;
    const int row0 = blockIdx.y * 128;
    const int col0 = blockIdx.x * 128;

    const int warpM = wid >> 2;
    const int warpN = wid & 3;
    const int qrow = lane >> 2;
    const int qk   = lane & 3;

    const int lm_row = lane & 7;
    const int lm_mat = lane >> 3;
    const int rowA_off = lm_row + ((lm_mat & 1) << 3);
    const int colA_off = (lm_mat >> 1) << 3;
    const int colB_off = lm_mat << 3;

    const uint32_t sA_u32 = smem_u32(sA);
    const uint32_t sB_u32 = smem_u32(sB);
    const uint32_t OBUF = (uint32_t)OBUFH * 2u;

    const __half* Ab[4];
    const __half* Bb[4];
    uint32_t dA[4], dB[4];
#pragma unroll
    for (int i = 0; i < 4; i++) {
        const int c = tid + (i << 8);
        const int row = c >> 3, part = (c & 7) << 3;
        Ab[i] = A  + (size_t)(row0 + row) * K + part;
        Bb[i] = BT + (size_t)(col0 + row) * K + part;
        dA[i] = sA_u32 + (uint32_t)(row * ASTR + part) * 2u;
        dB[i] = sB_u32 + (uint32_t)(row * ASTR + part) * 2u;
    }

    const uint32_t aLm0 = sA_u32 +
        (uint32_t)((warpM * 64 + rowA_off) * ASTR + colA_off) * 2u;
    const uint32_t bLm0 = sB_u32 +
        (uint32_t)((warpN * 32 + lm_row) * ASTR + colB_off) * 2u;

    float c[4][4][4];
#pragma unroll
    for (int mt = 0; mt < 4; mt++)
#pragma unroll
        for (int nt = 0; nt < 4; nt++)
#pragma unroll
            for (int r = 0; r < 4; r++) c[mt][nt][r] = 0.0f;

    const int niter = K >> 6;

#pragma unroll
    for (int s = 0; s < 2; s++) {
        const int k0 = s << 6;
        const uint32_t bo = (uint32_t)s * OBUF;
#pragma unroll
        for (int i = 0; i < 4; i++) {
            cp16(dA[i] + bo, Ab[i] + k0);
            cp16(dB[i] + bo, Bb[i] + k0);
        }
        CP_COMMIT();
    }

    int stage = 0, pstage = 2;
    for (int it = 0; it < niter; it++) {
        CP_WAIT1();
        __syncthreads();

        if (it + 2 < niter) {
            const int k0 = (it + 2) << 6;
            const uint32_t bo = (uint32_t)pstage * OBUF;
#pragma unroll
            for (int i = 0; i < 4; i++) {
                cp16(dA[i] + bo, Ab[i] + k0);
                cp16(dB[i] + bo, Bb[i] + k0);
            }
        }
        CP_COMMIT();

        const uint32_t aB = aLm0 + (uint32_t)stage * OBUF;
        const uint32_t bB = bLm0 + (uint32_t)stage * OBUF;

#pragma unroll
        for (int h2 = 0; h2 < 2; h2++) {
            uint32_t bfr[4][4];
#pragma unroll
            for (int nt = 0; nt < 4; nt++)
                ldsm_x4(bfr[nt], bB + (uint32_t)(nt * 8 * ASTR + h2 * 32) * 2u);
#pragma unroll
            for (int kh = 0; kh < 2; kh++) {
                uint32_t afr[4][4];
#pragma unroll
                for (int mt = 0; mt < 4; mt++)
                    ldsm_x4(afr[mt],
                            aB + (uint32_t)(mt * 16 * ASTR + h2 * 32 + kh * 16) * 2u);
#pragma unroll
                for (int mt = 0; mt < 4; mt++)
#pragma unroll
                    for (int nt = 0; nt < 4; nt++)
                        MMA_F16(c[mt][nt], afr[mt], &bfr[nt][2 * kh]);
            }
        }

        stage = (stage + 1 == NSTAGE) ? 0 : stage + 1;
        pstage = (pstage + 1 == NSTAGE) ? 0 : pstage + 1;
    }

    const float fac = (col0 < qlimit) ? qscale : 1.0f;
#pragma unroll
    for (int mt = 0; mt < 4; mt++) {
        const int r = row0 + warpM * 64 + mt * 16 + qrow;
#pragma unroll
        for (int nt = 0; nt < 4; nt++) {
            const int col = col0 + warpN * 32 + nt * 8 + qk * 2;
            if (OUT_HALF) {
                __half* Ch = (__half*)Cout;
                *reinterpret_cast<__half2*>(Ch + (size_t)r * N + col) =
                    __floats2half2_rn(c[mt][nt][0] * fac, c[mt][nt][1] * fac);
                *reinterpret_cast<__half2*>(Ch + (size_t)(r + 8) * N + col) =
                    __floats2half2_rn(c[mt][nt][2] * fac, c[mt][nt][3] * fac);
            } else {
                float* Cf = (float*)Cout;
                *reinterpret_cast<float2*>(Cf + (size_t)r * N + col) =
                    make_float2(c[mt][nt][0], c[mt][nt][1]);
                *reinterpret_cast<float2*>(Cf + (size_t)(r + 8) * N + col) =
                    make_float2(c[mt][nt][2], c[mt][nt][3]);
            }
        }
    }
}

// ===========================================================================
// fp16 tensor-core causal flash attention: register P, max-free softmax,
// trans-V, and NEW: f16 ACCUMULATORS for QK and per-tile PV (promoted to
// fp32 across tiles). Tests the double-rate f16-acc HMMA hypothesis.
// ===========================================================================
#define KSTR 72
#define PSTR 72
#define KBUF (64 * KSTR)
#define FLASH_SMEM ((2 * KBUF + 2 * KBUF + 128 * PSTR) * 2)

__global__ __launch_bounds__(256, 2)
void flash_attn_f16_kernel(const __half* __restrict__ qkv, __half* __restrict__ attout)
{
    extern __shared__ __half smem[];
    __half* sK = smem;
    __half* sV = smem + 2 * KBUF;
    __half* sQ = smem + 4 * KBUF;

    const int qb = (int)gridDim.x - 1 - (int)blockIdx.x;
    const int h = blockIdx.y;
    const int n = blockIdx.z;
    const int tid = threadIdx.x;
    const int wid = tid >> 5;
    const int lane = tid & 31;
    const int qrow = lane >> 2;
    const int qk = lane & 3;
    const int q0 = qb * 128;

    const int lm_row = lane & 7;
    const int lm_mat = lane >> 3;
    const int rowA_off = lm_row + ((lm_mat & 1) << 3);
    const int colA_off = (lm_mat >> 1) << 3;
    const int colB_off = lm_mat << 3;

    const size_t rs = QKVCOLS;
    const int ntiles = 2 * qb + 2;

    int krow[2], kpart[2];
#pragma unroll
    for (int i = 0; i < 2; i++) {
        const int c = tid + (i << 8);
        krow[i] = c >> 3;
        kpart[i] = (c & 7) << 3;
    }

    const uint32_t sK_u32 = smem_u32(sK);
    const uint32_t sV_u32 = smem_u32(sV);
    const uint32_t sQ_u32 = smem_u32(sQ);

    const __half* kg[2];
    const __half* vg[2];
    uint32_t dK[2], dV[2];
#pragma unroll
    for (int i = 0; i < 2; i++) {
        kg[i] = qkv + ((size_t)(n * TLEN) + krow[i]) * rs + DMODEL + h * DK + kpart[i];
        vg[i] = kg[i] + DMODEL;
        dK[i] = sK_u32 + (uint32_t)(krow[i] * KSTR + kpart[i]) * 2u;
        dV[i] = sV_u32 + (uint32_t)(krow[i] * KSTR + kpart[i]) * 2u;
    }

    {
#pragma unroll
        for (int i = 0; i < 2; i++) {
            cp16(dK[i], kg[i]);
            cp16(dV[i], vg[i]);
        }
        CP_COMMIT();
    }

    {
#pragma unroll
        for (int i = 0; i < 4; i++) {
            const int cq = tid + (i << 8);
            const int row = cq >> 3, part = (cq & 7) << 3;
            const __half* qg = qkv + ((size_t)(n * TLEN + q0 + row)) * rs + h * DK + part;
            *reinterpret_cast<uint4*>(sQ + row * PSTR + part) =
                *reinterpret_cast<const uint4*>(qg);
        }
    }
    __syncthreads();

    uint32_t qf[4][4];
    {
        const uint32_t qLm = sQ_u32 +
            (uint32_t)((wid * 16 + rowA_off) * PSTR + colA_off) * 2u;
#pragma unroll
        for (int kc = 0; kc < 4; kc++)
            ldsm_x4(qf[kc], qLm + (uint32_t)(kc * 16) * 2u);
    }

    float o[8][4];
#pragma unroll
    for (int nt = 0; nt < 8; nt++)
#pragma unroll
        for (int r = 0; r < 4; r++) o[nt][r] = 0.0f;

    float l0 = 0.0f, l1 = 0.0f;

    const int q_abs0 = q0 + wid * 16 + qrow;
    const int q_abs1 = q_abs0 + 8;
    const int wmax_kt = (q0 + wid * 16 + 15) >> 6;

    const uint32_t kLm0 = sK_u32 + (uint32_t)(lm_row * KSTR + colB_off) * 2u;
    const uint32_t vLm0 = sV_u32 + (uint32_t)(rowA_off * KSTR + colA_off) * 2u;

    for (int kt = 0; kt < ntiles; kt++) {
        CP_WAIT0();
        __syncthreads();

        if (kt + 1 < ntiles) {
            const uint32_t bo = ((kt + 1) & 1) * (uint32_t)(KBUF * 2);
#pragma unroll
            for (int i = 0; i < 2; i++) {
                cp16(dK[i] + bo, kg[i] + (size_t)((kt + 1) * 64) * rs);
                cp16(dV[i] + bo, vg[i] + (size_t)((kt + 1) * 64) * rs);
            }
            CP_COMMIT();
        }

        if (kt > wmax_kt) continue;

        const uint32_t kB = kLm0 + (kt & 1) * (uint32_t)(KBUF * 2);
        const uint32_t vB = vLm0 + (kt & 1) * (uint32_t)(KBUF * 2);

        // ---- S = Q K^T  (f16 accumulate; d-reduction is only 64) ----
        uint32_t s16[8][2];
#pragma unroll
        for (int nt = 0; nt < 8; nt++) {
            s16[nt][0] = 0u;
            s16[nt][1] = 0u;
            uint32_t bk[8];
            ldsm_x4(&bk[0], kB + (uint32_t)(nt * 8 * KSTR) * 2u);
            ldsm_x4(&bk[4], kB + (uint32_t)(nt * 8 * KSTR + 32) * 2u);
            MMA_F16A16(s16[nt], qf[0], &bk[0]);
            MMA_F16A16(s16[nt], qf[1], &bk[2]);
            MMA_F16A16(s16[nt], qf[2], &bk[4]);
            MMA_F16A16(s16[nt], qf[3], &bk[6]);
        }

        // unpack to fp32 for mask + softmax
        float s[8][4];
#pragma unroll
        for (int nt = 0; nt < 8; nt++) {
            float2 v0 = u2f2(s16[nt][0]);
            float2 v1 = u2f2(s16[nt][1]);
            s[nt][0] = v0.x; s[nt][1] = v0.y;
            s[nt][2] = v1.x; s[nt][3] = v1.y;
        }

        // ---- causal mask ----
        if (((kt << 6) + 63) > (q0 + wid * 16)) {
#pragma unroll
            for (int nt = 0; nt < 8; nt++) {
                const int c0 = (kt << 6) + (nt << 3) + (qk << 1);
                if (c0     > q_abs0) s[nt][0] = -1e30f;
                if (c0 + 1 > q_abs0) s[nt][1] = -1e30f;
                if (c0     > q_abs1) s[nt][2] = -1e30f;
                if (c0 + 1 > q_abs1) s[nt][3] = -1e30f;
            }
        }

        // ---- max-free softmax ----
        float rs0 = 0.0f, rs1 = 0.0f;
#pragma unroll
        for (int nt = 0; nt < 8; nt++) {
            s[nt][0] = ex2(s[nt][0]);
            s[nt][1] = ex2(s[nt][1]);
            s[nt][2] = ex2(s[nt][2]);
            s[nt][3] = ex2(s[nt][3]);
            rs0 += s[nt][0] + s[nt][1];
            rs1 += s[nt][2] + s[nt][3];
        }
        rs0 += __shfl_xor_sync(0xffffffffu, rs0, 1);
        rs0 += __shfl_xor_sync(0xffffffffu, rs0, 2);
        rs1 += __shfl_xor_sync(0xffffffffu, rs1, 1);
        rs1 += __shfl_xor_sync(0xffffffffu, rs1, 2);
        l0 += rs0;
        l1 += rs1;

        // ---- P A-fragments from S ----
        uint32_t afP[4][4];
#pragma unroll
        for (int kvp = 0; kvp < 4; kvp++) {
            afP[kvp][0] = h2u(s[2 * kvp][0],     s[2 * kvp][1]);
            afP[kvp][1] = h2u(s[2 * kvp][2],     s[2 * kvp][3]);
            afP[kvp][2] = h2u(s[2 * kvp + 1][0], s[2 * kvp + 1][1]);
            afP[kvp][3] = h2u(s[2 * kvp + 1][2], s[2 * kvp + 1][3]);
        }

        // ---- O_tile = P V  (f16 accumulate, t-reduction 64 per tile) ----
        uint32_t o16[8][2];
#pragma unroll
        for (int nt = 0; nt < 8; nt++) { o16[nt][0] = 0u; o16[nt][1] = 0u; }
#pragma unroll
        for (int tc = 0; tc < 4; tc++) {
#pragma unroll
            for (int dp = 0; dp < 4; dp++) {
                uint32_t bv[4];
                ldsm_x4_trans(bv, vB + (uint32_t)(tc * 16 * KSTR + dp * 16) * 2u);
                MMA_F16A16(o16[2 * dp],     afP[tc], &bv[0]);
                MMA_F16A16(o16[2 * dp + 1], afP[tc], &bv[2]);
            }
        }

        // promote tile result into fp32 accumulators
#pragma unroll
        for (int nt = 0; nt < 8; nt++) {
            float2 v0 = u2f2(o16[nt][0]);
            float2 v1 = u2f2(o16[nt][1]);
            o[nt][0] += v0.x; o[nt][1] += v0.y;
            o[nt][2] += v1.x; o[nt][3] += v1.y;
        }
    }

    const float inv0 = 1.0f / l0;
    const float inv1 = 1.0f / l1;
    __half* ob = attout + ((size_t)(n * TLEN + q0 + wid * 16 + qrow)) * DMODEL
                 + h * DK + (qk << 1);
#pragma unroll
    for (int nt = 0; nt < 8; nt++) {
        *reinterpret_cast<__half2*>(ob + nt * 8) =
            __floats2half2_rn(o[nt][0] * inv0, o[nt][1] * inv0);
        *reinterpret_cast<__half2*>(ob + (size_t)8 * DMODEL + nt * 8) =
            __floats2half2_rn(o[nt][2] * inv1, o[nt][3] * inv1);
    }
}

// ---------------------------------------------------------------------------
// Launch
// ---------------------------------------------------------------------------
extern "C" void kernel_launch(void* const* d_in, const int* in_sizes, int n_in,
                              void* d_out, int out_size)
{
    const float* z    = (const float*)d_in[0];
    const float* Wqkv = (const float*)d_in[1];
    const float* Wout = (const float*)d_in[2];
    float* out = (float*)d_out;

    void *pqkv, *patt, *pzr, *pwq, *pwo;
    cudaGetSymbolAddress(&pqkv, g_qkv);
    cudaGetSymbolAddress(&patt, g_att);
    cudaGetSymbolAddress(&pzr, g_zr);
    cudaGetSymbolAddress(&pwq, g_wtqkv);
    cudaGetSymbolAddress(&pwo, g_wtout);
    __half* qkv = (__half*)pqkv;
    __half* att = (__half*)patt;
    __half* zr  = (__half*)pzr;
    __half* wtq = (__half*)pwq;
    __half* wto = (__half*)pwo;

    cudaFuncSetAttribute(f16_gemm_kernel<1>,
                         cudaFuncAttributeMaxDynamicSharedMemorySize, GEMM_SMEM);
    cudaFuncSetAttribute(f16_gemm_kernel<0>,
                         cudaFuncAttributeMaxDynamicSharedMemorySize, GEMM_SMEM);
    cudaFuncSetAttribute(flash_attn_f16_kernel,
                         cudaFuncAttributeMaxDynamicSharedMemorySize, FLASH_SMEM);

    // 0) z -> fp16; weights transpose -> fp16
    {
        const int n4 = MROWS * DMODEL / 4;
        round_copy_kernel<<<(n4 + 255) / 256, 256>>>(
            (const float4*)z, (__half2*)zr, n4);
    }
    transpose_round_kernel<<<dim3(QKVCOLS / 32, DMODEL / 32), dim3(32, 8)>>>(
        Wqkv, wtq, DMODEL, QKVCOLS);
    transpose_round_kernel<<<dim3(DMODEL / 32, DMODEL / 32), dim3(32, 8)>>>(
        Wout, wto, DMODEL, DMODEL);

    // 1) qkv = z @ Wqkv  (fp16 out; Q cols pre-scaled by QSCALE)
    f16_gemm_kernel<1><<<dim3(QKVCOLS / 128, MROWS / 128), 256, GEMM_SMEM>>>(
        zr, wtq, (void*)qkv, MROWS, QKVCOLS, DMODEL, DMODEL, QSCALE);

    // 2) causal flash attention (register P, max-free softmax, trans-V,
    //    f16 accumulators with per-tile fp32 promotion)
    flash_attn_f16_kernel<<<dim3(TLEN / 128, NH, NB), 256, FLASH_SMEM>>>(qkv, att);

    // 3) out = att @ Wout  (fp32 out)
    f16_gemm_kernel<0><<<dim3(DMODEL / 128, MROWS / 128), 256, GEMM_SMEM>>>(
        att, wto, (void*)out, MROWS, DMODEL, DMODEL, 0, 1.0f);
}

// round 16
// speedup vs baseline: 1.0534x; 1.0534x over previous
#include <cuda_runtime.h>
#include <cuda_fp16.h>
#include <cstdint>
#include <cstddef>

// Problem constants
#define NB   4
#define TLEN 2048
#define DMODEL 1024
#define NH   16
#define DK   64
#define MROWS (NB * TLEN)        // 8192
#define QKVCOLS (3 * DMODEL)     // 3072

// Q pre-scale: 1/sqrt(64) * log2(e)  (softmax runs in exp2 domain)
#define QSCALE 0.1803368801111204f

// Scratch (device globals) — fp16 datapath
__device__ __half g_qkv[(size_t)MROWS * QKVCOLS];       // 50.3 MB (Q pre-scaled)
__device__ __half g_att[(size_t)MROWS * DMODEL];        // 16.8 MB
__device__ __half g_zr[(size_t)MROWS * DMODEL];         // 16.8 MB
__device__ __half g_wtqkv[(size_t)QKVCOLS * DMODEL];    // 6.3 MB
__device__ __half g_wtout[(size_t)DMODEL * DMODEL];     // 2.1 MB

__device__ __forceinline__ float ex2(float x) {
    float y;
    asm("ex2.approx.f32 %0, %1;" : "=f"(y) : "f"(x));
    return y;
}

__device__ __forceinline__ uint32_t smem_u32(const void* p) {
    uint32_t a;
    asm("{ .reg .u64 t; cvta.to.shared.u64 t, %1; cvt.u32.u64 %0, t; }"
        : "=r"(a) : "l"(p));
    return a;
}

__device__ __forceinline__ void cp16(uint32_t dst, const void* src) {
    asm volatile("cp.async.cg.shared.global [%0], [%1], 16;"
                 :: "r"(dst), "l"(src));
}
#define CP_COMMIT() asm volatile("cp.async.commit_group;" ::: "memory")
#define CP_WAIT0()  asm volatile("cp.async.wait_group 0;" ::: "memory")
#define CP_WAIT1()  asm volatile("cp.async.wait_group 1;" ::: "memory")

__device__ __forceinline__ void ldsm_x4(uint32_t* r, uint32_t addr) {
    asm volatile("ldmatrix.sync.aligned.m8n8.x4.shared.b16 {%0,%1,%2,%3}, [%4];"
                 : "=r"(r[0]), "=r"(r[1]), "=r"(r[2]), "=r"(r[3]) : "r"(addr));
}

__device__ __forceinline__ void ldsm_x4_trans(uint32_t* r, uint32_t addr) {
    asm volatile("ldmatrix.sync.aligned.m8n8.x4.trans.shared.b16 {%0,%1,%2,%3}, [%4];"
                 : "=r"(r[0]), "=r"(r[1]), "=r"(r[2]), "=r"(r[3]) : "r"(addr));
}

__device__ __forceinline__ uint32_t h2u(float a, float b) {
    __half2 h = __floats2half2_rn(a, b);
    return *reinterpret_cast<uint32_t*>(&h);
}

#define MMA_F16(c, a, b)                                                      \
    asm volatile(                                                             \
        "mma.sync.aligned.m16n8k16.row.col.f32.f16.f16.f32 "                  \
        "{%0,%1,%2,%3}, {%4,%5,%6,%7}, {%8,%9}, {%0,%1,%2,%3};"               \
        : "+f"((c)[0]), "+f"((c)[1]), "+f"((c)[2]), "+f"((c)[3])              \
        : "r"((a)[0]), "r"((a)[1]), "r"((a)[2]), "r"((a)[3]),                 \
          "r"((b)[0]), "r"((b)[1]))

// ===========================================================================
// Fused prep: z->fp16 copy + Wqkv^T + Wout^T in ONE launch (flat grid).
// blocks [0, 8192): z copy (256 float4 each)
// blocks [8192, 11264): Wqkv transpose tiles (96 x 32)
// blocks [11264, 12288): Wout transpose tiles (32 x 32)
// ===========================================================================
#define PREP_ZBLOCKS   8192
#define PREP_WQBLOCKS  3072
#define PREP_TOTAL     (PREP_ZBLOCKS + PREP_WQBLOCKS + 1024)

__global__ __launch_bounds__(256)
void prep_kernel(const float* __restrict__ z, __half2* __restrict__ zr,
                 const float* __restrict__ Wqkv, __half* __restrict__ wtq,
                 const float* __restrict__ Wout, __half* __restrict__ wto)
{
    __shared__ float tile[32][33];
    const int b = blockIdx.x;
    const int tid = threadIdx.x;

    if (b < PREP_ZBLOCKS) {
        const int i = b * 256 + tid;   // < 2,097,152 float4s
        float4 v = reinterpret_cast<const float4*>(z)[i];
        zr[2 * i]     = __floats2half2_rn(v.x, v.y);
        zr[2 * i + 1] = __floats2half2_rn(v.z, v.w);
        return;
    }

    const float* W;
    __half* WT;
    int bx, by, K, N;
    if (b < PREP_ZBLOCKS + PREP_WQBLOCKS) {
        const int bb = b - PREP_ZBLOCKS;
        W = Wqkv; WT = wtq; K = DMODEL; N = QKVCOLS;
        bx = (bb % 96) * 32; by = (bb / 96) * 32;
    } else {
        const int bb = b - PREP_ZBLOCKS - PREP_WQBLOCKS;
        W = Wout; WT = wto; K = DMODEL; N = DMODEL;
        bx = (bb % 32) * 32; by = (bb / 32) * 32;
    }
    const int tx = tid & 31;
    const int ty = tid >> 5;   // 0..7
#pragma unroll
    for (int i = 0; i < 32; i += 8)
        tile[ty + i][tx] = W[(size_t)(by + ty + i) * N + bx + tx];
    __syncthreads();
#pragma unroll
    for (int i = 0; i < 32; i += 8)
        WT[(size_t)(bx + ty + i) * K + by + tx] = __float2half_rn(tile[tx][ty + i]);
}

// ===========================================================================
// 3-stage pipelined fp16 GEMM, CTA 128x128, BK=64 (round-14 verified best)
// ===========================================================================
#define ASTR 72
#define NSTAGE 3
#define OBUFH (128 * ASTR)
#define GEMM_SMEM (NSTAGE * 2 * OBUFH * 2)   // 110592 B

template <int OUT_HALF>
__global__ __launch_bounds__(256, 2)
void f16_gemm_kernel(const __half* __restrict__ A, const __half* __restrict__ BT,
                     void* __restrict__ Cout, int M, int N, int K,
                     int qlimit, float qscale)
{
    extern __shared__ __half hs[];
    __half* sA = hs;
    __half* sB = hs + NSTAGE * OBUFH;

    const int tid = threadIdx.x;
    const int wid = tid >> 5;
    const int lane = tid & 31;
    const int row0 = blockIdx.y * 128;
    const int col0 = blockIdx.x * 128;

    const int warpM = wid >> 2;
    const int warpN = wid & 3;
    const int qrow = lane >> 2;
    const int qk   = lane & 3;

    const int lm_row = lane & 7;
    const int lm_mat = lane >> 3;
    const int rowA_off = lm_row + ((lm_mat & 1) << 3);
    const int colA_off = (lm_mat >> 1) << 3;
    const int colB_off = lm_mat << 3;

    const uint32_t sA_u32 = smem_u32(sA);
    const uint32_t sB_u32 = smem_u32(sB);
    const uint32_t OBUF = (uint32_t)OBUFH * 2u;

    const __half* Ab[4];
    const __half* Bb[4];
    uint32_t dA[4], dB[4];
#pragma unroll
    for (int i = 0; i < 4; i++) {
        const int c = tid + (i << 8);
        const int row = c >> 3, part = (c & 7) << 3;
        Ab[i] = A  + (size_t)(row0 + row) * K + part;
        Bb[i] = BT + (size_t)(col0 + row) * K + part;
        dA[i] = sA_u32 + (uint32_t)(row * ASTR + part) * 2u;
        dB[i] = sB_u32 + (uint32_t)(row * ASTR + part) * 2u;
    }

    const uint32_t aLm0 = sA_u32 +
        (uint32_t)((warpM * 64 + rowA_off) * ASTR + colA_off) * 2u;
    const uint32_t bLm0 = sB_u32 +
        (uint32_t)((warpN * 32 + lm_row) * ASTR + colB_off) * 2u;

    float c[4][4][4];
#pragma unroll
    for (int mt = 0; mt < 4; mt++)
#pragma unroll
        for (int nt = 0; nt < 4; nt++)
#pragma unroll
            for (int r = 0; r < 4; r++) c[mt][nt][r] = 0.0f;

    const int niter = K >> 6;

#pragma unroll
    for (int s = 0; s < 2; s++) {
        const int k0 = s << 6;
        const uint32_t bo = (uint32_t)s * OBUF;
#pragma unroll
        for (int i = 0; i < 4; i++) {
            cp16(dA[i] + bo, Ab[i] + k0);
            cp16(dB[i] + bo, Bb[i] + k0);
        }
        CP_COMMIT();
    }

    int stage = 0, pstage = 2;
    for (int it = 0; it < niter; it++) {
        CP_WAIT1();
        __syncthreads();

        if (it + 2 < niter) {
            const int k0 = (it + 2) << 6;
            const uint32_t bo = (uint32_t)pstage * OBUF;
#pragma unroll
            for (int i = 0; i < 4; i++) {
                cp16(dA[i] + bo, Ab[i] + k0);
                cp16(dB[i] + bo, Bb[i] + k0);
            }
        }
        CP_COMMIT();

        const uint32_t aB = aLm0 + (uint32_t)stage * OBUF;
        const uint32_t bB = bLm0 + (uint32_t)stage * OBUF;

#pragma unroll
        for (int h2 = 0; h2 < 2; h2++) {
            uint32_t bfr[4][4];
#pragma unroll
            for (int nt = 0; nt < 4; nt++)
                ldsm_x4(bfr[nt], bB + (uint32_t)(nt * 8 * ASTR + h2 * 32) * 2u);
#pragma unroll
            for (int kh = 0; kh < 2; kh++) {
                uint32_t afr[4][4];
#pragma unroll
                for (int mt = 0; mt < 4; mt++)
                    ldsm_x4(afr[mt],
                            aB + (uint32_t)(mt * 16 * ASTR + h2 * 32 + kh * 16) * 2u);
#pragma unroll
                for (int mt = 0; mt < 4; mt++)
#pragma unroll
                    for (int nt = 0; nt < 4; nt++)
                        MMA_F16(c[mt][nt], afr[mt], &bfr[nt][2 * kh]);
            }
        }

        stage = (stage + 1 == NSTAGE) ? 0 : stage + 1;
        pstage = (pstage + 1 == NSTAGE) ? 0 : pstage + 1;
    }

    const float fac = (col0 < qlimit) ? qscale : 1.0f;
#pragma unroll
    for (int mt = 0; mt < 4; mt++) {
        const int r = row0 + warpM * 64 + mt * 16 + qrow;
#pragma unroll
        for (int nt = 0; nt < 4; nt++) {
            const int col = col0 + warpN * 32 + nt * 8 + qk * 2;
            if (OUT_HALF) {
                __half* Ch = (__half*)Cout;
                *reinterpret_cast<__half2*>(Ch + (size_t)r * N + col) =
                    __floats2half2_rn(c[mt][nt][0] * fac, c[mt][nt][1] * fac);
                *reinterpret_cast<__half2*>(Ch + (size_t)(r + 8) * N + col) =
                    __floats2half2_rn(c[mt][nt][2] * fac, c[mt][nt][3] * fac);
            } else {
                float* Cf = (float*)Cout;
                *reinterpret_cast<float2*>(Cf + (size_t)r * N + col) =
                    make_float2(c[mt][nt][0], c[mt][nt][1]);
                *reinterpret_cast<float2*>(Cf + (size_t)(r + 8) * N + col) =
                    make_float2(c[mt][nt][2], c[mt][nt][3]);
            }
        }
    }
}

// ===========================================================================
// fp16 tensor-core causal flash attention (round-14 verified: f32 accum,
// register P, max-free softmax, trans-V)
// ===========================================================================
#define KSTR 72
#define PSTR 72
#define KBUF (64 * KSTR)
#define FLASH_SMEM ((2 * KBUF + 2 * KBUF + 128 * PSTR) * 2)

__global__ __launch_bounds__(256, 2)
void flash_attn_f16_kernel(const __half* __restrict__ qkv, __half* __restrict__ attout)
{
    extern __shared__ __half smem[];
    __half* sK = smem;
    __half* sV = smem + 2 * KBUF;
    __half* sQ = smem + 4 * KBUF;

    const int qb = (int)gridDim.x - 1 - (int)blockIdx.x;
    const int h = blockIdx.y;
    const int n = blockIdx.z;
    const int tid = threadIdx.x;
    const int wid = tid >> 5;
    const int lane = tid & 31;
    const int qrow = lane >> 2;
    const int qk = lane & 3;
    const int q0 = qb * 128;

    const int lm_row = lane & 7;
    const int lm_mat = lane >> 3;
    const int rowA_off = lm_row + ((lm_mat & 1) << 3);
    const int colA_off = (lm_mat >> 1) << 3;
    const int colB_off = lm_mat << 3;

    const size_t rs = QKVCOLS;
    const int ntiles = 2 * qb + 2;

    int krow[2], kpart[2];
#pragma unroll
    for (int i = 0; i < 2; i++) {
        const int c = tid + (i << 8);
        krow[i] = c >> 3;
        kpart[i] = (c & 7) << 3;
    }

    const uint32_t sK_u32 = smem_u32(sK);
    const uint32_t sV_u32 = smem_u32(sV);
    const uint32_t sQ_u32 = smem_u32(sQ);

    const __half* kg[2];
    const __half* vg[2];
    uint32_t dK[2], dV[2];
#pragma unroll
    for (int i = 0; i < 2; i++) {
        kg[i] = qkv + ((size_t)(n * TLEN) + krow[i]) * rs + DMODEL + h * DK + kpart[i];
        vg[i] = kg[i] + DMODEL;
        dK[i] = sK_u32 + (uint32_t)(krow[i] * KSTR + kpart[i]) * 2u;
        dV[i] = sV_u32 + (uint32_t)(krow[i] * KSTR + kpart[i]) * 2u;
    }

    {
#pragma unroll
        for (int i = 0; i < 2; i++) {
            cp16(dK[i], kg[i]);
            cp16(dV[i], vg[i]);
        }
        CP_COMMIT();
    }

    {
#pragma unroll
        for (int i = 0; i < 4; i++) {
            const int cq = tid + (i << 8);
            const int row = cq >> 3, part = (cq & 7) << 3;
            const __half* qg = qkv + ((size_t)(n * TLEN + q0 + row)) * rs + h * DK + part;
            *reinterpret_cast<uint4*>(sQ + row * PSTR + part) =
                *reinterpret_cast<const uint4*>(qg);
        }
    }
    __syncthreads();

    uint32_t qf[4][4];
    {
        const uint32_t qLm = sQ_u32 +
            (uint32_t)((wid * 16 + rowA_off) * PSTR + colA_off) * 2u;
#pragma unroll
        for (int kc = 0; kc < 4; kc++)
            ldsm_x4(qf[kc], qLm + (uint32_t)(kc * 16) * 2u);
    }

    float o[8][4];
#pragma unroll
    for (int nt = 0; nt < 8; nt++)
#pragma unroll
        for (int r = 0; r < 4; r++) o[nt][r] = 0.0f;

    float l0 = 0.0f, l1 = 0.0f;

    const int q_abs0 = q0 + wid * 16 + qrow;
    const int q_abs1 = q_abs0 + 8;
    const int wmax_kt = (q0 + wid * 16 + 15) >> 6;

    const uint32_t kLm0 = sK_u32 + (uint32_t)(lm_row * KSTR + colB_off) * 2u;
    const uint32_t vLm0 = sV_u32 + (uint32_t)(rowA_off * KSTR + colA_off) * 2u;

    for (int kt = 0; kt < ntiles; kt++) {
        CP_WAIT0();
        __syncthreads();

        if (kt + 1 < ntiles) {
            const uint32_t bo = ((kt + 1) & 1) * (uint32_t)(KBUF * 2);
#pragma unroll
            for (int i = 0; i < 2; i++) {
                cp16(dK[i] + bo, kg[i] + (size_t)((kt + 1) * 64) * rs);
                cp16(dV[i] + bo, vg[i] + (size_t)((kt + 1) * 64) * rs);
            }
            CP_COMMIT();
        }

        if (kt > wmax_kt) continue;

        const uint32_t kB = kLm0 + (kt & 1) * (uint32_t)(KBUF * 2);
        const uint32_t vB = vLm0 + (kt & 1) * (uint32_t)(KBUF * 2);

        float s[8][4];
#pragma unroll
        for (int nt = 0; nt < 8; nt++)
#pragma unroll
            for (int r = 0; r < 4; r++) s[nt][r] = 0.0f;

#pragma unroll
        for (int nt = 0; nt < 8; nt++) {
            uint32_t bk[8];
            ldsm_x4(&bk[0], kB + (uint32_t)(nt * 8 * KSTR) * 2u);
            ldsm_x4(&bk[4], kB + (uint32_t)(nt * 8 * KSTR + 32) * 2u);
            MMA_F16(s[nt], qf[0], &bk[0]);
            MMA_F16(s[nt], qf[1], &bk[2]);
            MMA_F16(s[nt], qf[2], &bk[4]);
            MMA_F16(s[nt], qf[3], &bk[6]);
        }

        if (((kt << 6) + 63) > (q0 + wid * 16)) {
#pragma unroll
            for (int nt = 0; nt < 8; nt++) {
                const int c0 = (kt << 6) + (nt << 3) + (qk << 1);
                if (c0     > q_abs0) s[nt][0] = -1e30f;
                if (c0 + 1 > q_abs0) s[nt][1] = -1e30f;
                if (c0     > q_abs1) s[nt][2] = -1e30f;
                if (c0 + 1 > q_abs1) s[nt][3] = -1e30f;
            }
        }

        float rs0 = 0.0f, rs1 = 0.0f;
#pragma unroll
        for (int nt = 0; nt < 8; nt++) {
            s[nt][0] = ex2(s[nt][0]);
            s[nt][1] = ex2(s[nt][1]);
            s[nt][2] = ex2(s[nt][2]);
            s[nt][3] = ex2(s[nt][3]);
            rs0 += s[nt][0] + s[nt][1];
            rs1 += s[nt][2] + s[nt][3];
        }
        rs0 += __shfl_xor_sync(0xffffffffu, rs0, 1);
        rs0 += __shfl_xor_sync(0xffffffffu, rs0, 2);
        rs1 += __shfl_xor_sync(0xffffffffu, rs1, 1);
        rs1 += __shfl_xor_sync(0xffffffffu, rs1, 2);
        l0 += rs0;
        l1 += rs1;

        uint32_t afP[4][4];
#pragma unroll
        for (int kvp = 0; kvp < 4; kvp++) {
            afP[kvp][0] = h2u(s[2 * kvp][0],     s[2 * kvp][1]);
            afP[kvp][1] = h2u(s[2 * kvp][2],     s[2 * kvp][3]);
            afP[kvp][2] = h2u(s[2 * kvp + 1][0], s[2 * kvp + 1][1]);
            afP[kvp][3] = h2u(s[2 * kvp + 1][2], s[2 * kvp + 1][3]);
        }

#pragma unroll
        for (int tc = 0; tc < 4; tc++) {
#pragma unroll
            for (int dp = 0; dp < 4; dp++) {
                uint32_t bv[4];
                ldsm_x4_trans(bv, vB + (uint32_t)(tc * 16 * KSTR + dp * 16) * 2u);
                MMA_F16(o[2 * dp],     afP[tc], &bv[0]);
                MMA_F16(o[2 * dp + 1], afP[tc], &bv[2]);
            }
        }
    }

    const float inv0 = 1.0f / l0;
    const float inv1 = 1.0f / l1;
    __half* ob = attout + ((size_t)(n * TLEN + q0 + wid * 16 + qrow)) * DMODEL
                 + h * DK + (qk << 1);
#pragma unroll
    for (int nt = 0; nt < 8; nt++) {
        *reinterpret_cast<__half2*>(ob + nt * 8) =
            __floats2half2_rn(o[nt][0] * inv0, o[nt][1] * inv0);
        *reinterpret_cast<__half2*>(ob + (size_t)8 * DMODEL + nt * 8) =
            __floats2half2_rn(o[nt][2] * inv1, o[nt][3] * inv1);
    }
}

// ---------------------------------------------------------------------------
// Launch
// ---------------------------------------------------------------------------
extern "C" void kernel_launch(void* const* d_in, const int* in_sizes, int n_in,
                              void* d_out, int out_size)
{
    const float* z    = (const float*)d_in[0];
    const float* Wqkv = (const float*)d_in[1];
    const float* Wout = (const float*)d_in[2];
    float* out = (float*)d_out;

    void *pqkv, *patt, *pzr, *pwq, *pwo;
    cudaGetSymbolAddress(&pqkv, g_qkv);
    cudaGetSymbolAddress(&patt, g_att);
    cudaGetSymbolAddress(&pzr, g_zr);
    cudaGetSymbolAddress(&pwq, g_wtqkv);
    cudaGetSymbolAddress(&pwo, g_wtout);
    __half* qkv = (__half*)pqkv;
    __half* att = (__half*)patt;
    __half* zr  = (__half*)pzr;
    __half* wtq = (__half*)pwq;
    __half* wto = (__half*)pwo;

    cudaFuncSetAttribute(f16_gemm_kernel<1>,
                         cudaFuncAttributeMaxDynamicSharedMemorySize, GEMM_SMEM);
    cudaFuncSetAttribute(f16_gemm_kernel<0>,
                         cudaFuncAttributeMaxDynamicSharedMemorySize, GEMM_SMEM);
    cudaFuncSetAttribute(flash_attn_f16_kernel,
                         cudaFuncAttributeMaxDynamicSharedMemorySize, FLASH_SMEM);

    // 0) fused prep: z->fp16 + both weight transposes (one launch)
    prep_kernel<<<PREP_TOTAL, 256>>>(z, (__half2*)zr, Wqkv, wtq, Wout, wto);

    // 1) qkv = z @ Wqkv  (fp16 out; Q cols pre-scaled by QSCALE)
    f16_gemm_kernel<1><<<dim3(QKVCOLS / 128, MROWS / 128), 256, GEMM_SMEM>>>(
        zr, wtq, (void*)qkv, MROWS, QKVCOLS, DMODEL, DMODEL, QSCALE);

    // 2) causal flash attention
    flash_attn_f16_kernel<<<dim3(TLEN / 128, NH, NB), 256, FLASH_SMEM>>>(qkv, att);

    // 3) out = att @ Wout  (fp32 out)
    f16_gemm_kernel<0><<<dim3(DMODEL / 128, MROWS / 128), 256, GEMM_SMEM>>>(
        att, wto, (void*)out, MROWS, DMODEL, DMODEL, 0, 1.0f);
}